// round 1
// baseline (speedup 1.0000x reference)
#include <cuda_runtime.h>
#include <math.h>

#define NN 262144
#define LL 128
#define LOG_L 7
#define CC (NN / LL)   // 2048 chunks
#define MM 2048
#define GRAV 9.81007f

struct FSumm { float4 dq; float Ax,Ay,Az,Px,Py,Pz,T,G; };
struct DSumm { float4 dq; double Ax,Ay,Az,Px,Py,Pz,T,G; };

__device__ float4 g_pack[2 * NN];      // [dq(4)] [a.xyz, dt]
__device__ FSumm  g_summ[CC];
__device__ float4 g_sq[CC];
__device__ double g_sv[3 * CC];
__device__ double g_sp[3 * CC];
__device__ double g_part[2 * MM];

// ---------------- quaternion helpers (float) ----------------
__device__ __forceinline__ float4 qmul4(float4 q, float4 r) {
    return make_float4(
        q.w*r.x + q.x*r.w + q.y*r.z - q.z*r.y,
        q.w*r.y - q.x*r.z + q.y*r.w + q.z*r.x,
        q.w*r.z + q.x*r.y - q.y*r.x + q.z*r.w,
        q.w*r.w - q.x*r.x - q.y*r.y - q.z*r.z);
}
__device__ __forceinline__ float4 qnorm4(float4 q) {
    float n = rsqrtf(q.x*q.x + q.y*q.y + q.z*q.z + q.w*q.w);
    return make_float4(q.x*n, q.y*n, q.z*n, q.w*n);
}
__device__ __forceinline__ float3 qrot3(float4 q, float3 v) {
    float tx = 2.0f*(q.y*v.z - q.z*v.y);
    float ty = 2.0f*(q.z*v.x - q.x*v.z);
    float tz = 2.0f*(q.x*v.y - q.y*v.x);
    return make_float3(
        v.x + q.w*tx + (q.y*tz - q.z*ty),
        v.y + q.w*ty + (q.z*tx - q.x*tz),
        v.z + q.w*tz + (q.x*ty - q.y*tx));
}
// rotate double vector by float quat (promoted)
__device__ __forceinline__ void qrotd(float4 qf, double vx, double vy, double vz,
                                      double& ox, double& oy, double& oz) {
    double qx = qf.x, qy = qf.y, qz = qf.z, qw = qf.w;
    double tx = 2.0*(qy*vz - qz*vy);
    double ty = 2.0*(qz*vx - qx*vz);
    double tz = 2.0*(qx*vy - qy*vx);
    ox = vx + qw*tx + (qy*tz - qz*ty);
    oy = vy + qw*ty + (qz*tx - qx*tz);
    oz = vz + qw*tz + (qx*ty - qy*tx);
}

// ---------------- kernel 0: pack + exp_so3 ----------------
__global__ void k_pack(const float* __restrict__ acc, const float* __restrict__ gyr,
                       const float* __restrict__ ab,  const float* __restrict__ gb,
                       const float* __restrict__ dts) {
    int i = blockIdx.x * blockDim.x + threadIdx.x;
    if (i >= NN) return;
    float ax = acc[3*i+0] - ab[0];
    float ay = acc[3*i+1] - ab[1];
    float az = acc[3*i+2] - ab[2];
    float dt = dts[i];
    float px = (gyr[3*i+0] - gb[0]) * dt;
    float py = (gyr[3*i+1] - gb[1]) * dt;
    float pz = (gyr[3*i+2] - gb[2]) * dt;
    float th2 = px*px + py*py + pz*pz;
    float half = 0.5f * sqrtf(th2);
    float h2 = half * half;
    float sc;
    if (half > 1e-3f) sc = sinf(half) / half;
    else              sc = 1.0f - h2*(1.0f/6.0f)*(1.0f - h2*0.05f); // 1 - h2/6 + h4/120
    float k = 0.5f * sc;
    float w = cosf(half);
    g_pack[2*i]   = make_float4(px*k, py*k, pz*k, w);
    g_pack[2*i+1] = make_float4(ax, ay, az, dt);
}

// ---------------- kernel 1: per-chunk summaries ----------------
__global__ void k_chunk() {
    int c = blockIdx.x * blockDim.x + threadIdx.x;
    if (c >= CC) return;
    const float4* base = g_pack + 2 * (c << LOG_L);
    float4 q = make_float4(0.f, 0.f, 0.f, 1.f);
    float Ax=0.f, Ay=0.f, Az=0.f, Px=0.f, Py=0.f, Pz=0.f, T=0.f, G=0.f;
#pragma unroll 4
    for (int s = 0; s < LL; s++) {
        float4 dqi = base[2*s];
        float4 a4  = base[2*s+1];
        float3 b = qrot3(q, make_float3(a4.x, a4.y, a4.z));
        float dt = a4.w;
        float h  = 0.5f * dt * dt;
        Px += Ax*dt + b.x*h;  Py += Ay*dt + b.y*h;  Pz += Az*dt + b.z*h;
        G  += T*dt + h;
        Ax += b.x*dt;  Ay += b.y*dt;  Az += b.z*dt;
        T  += dt;
        q = qmul4(q, dqi);   // renorm deferred: |q| drifts <1e-6 over 128 steps
    }
    q = qnorm4(q);
    FSumm s; s.dq=q; s.Ax=Ax; s.Ay=Ay; s.Az=Az; s.Px=Px; s.Py=Py; s.Pz=Pz; s.T=T; s.G=G;
    g_summ[c] = s;
}

// ---------------- kernel 2: scan of summaries -> chunk-start states ----------------
__device__ __forceinline__ DSumm dident() {
    DSumm d; d.dq = make_float4(0.f,0.f,0.f,1.f);
    d.Ax=d.Ay=d.Az=d.Px=d.Py=d.Pz=0.0; d.T=d.G=0.0; return d;
}
__device__ __forceinline__ DSumm dload(int c) {
    FSumm f = g_summ[c];
    DSumm d; d.dq=f.dq; d.Ax=f.Ax; d.Ay=f.Ay; d.Az=f.Az;
    d.Px=f.Px; d.Py=f.Py; d.Pz=f.Pz; d.T=f.T; d.G=f.G; return d;
}
__device__ __forceinline__ DSumm dcombine(const DSumm& a, const DSumm& b) {
    DSumm o;
    o.T = a.T + b.T;
    o.G = a.G + a.T * b.T + b.G;
    double rx, ry, rz;
    qrotd(a.dq, b.Ax, b.Ay, b.Az, rx, ry, rz);
    o.Ax = a.Ax + rx;  o.Ay = a.Ay + ry;  o.Az = a.Az + rz;
    qrotd(a.dq, b.Px, b.Py, b.Pz, rx, ry, rz);
    o.Px = a.Px + a.Ax * b.T + rx;
    o.Py = a.Py + a.Ay * b.T + ry;
    o.Pz = a.Pz + a.Az * b.T + rz;
    o.dq = qnorm4(qmul4(a.dq, b.dq));
    return o;
}

__global__ void k_scan(const float* __restrict__ q0p, const float* __restrict__ p0p,
                       const float* __restrict__ v0p) {
    __shared__ DSumm sh[256];
    int t = threadIdx.x;
    // phase 1: serial total of this thread's 8 chunks
    DSumm run = dident();
    for (int k = 0; k < 8; k++) run = dcombine(run, dload(8*t + k));
    sh[t] = run;
    __syncthreads();
    // Hillis-Steele inclusive scan over 256 thread-totals
    for (int off = 1; off < 256; off <<= 1) {
        DSumm v = sh[t];
        if (t >= off) v = dcombine(sh[t - off], v);
        __syncthreads();
        sh[t] = v;
        __syncthreads();
    }
    DSumm ex = (t == 0) ? dident() : sh[t - 1];
    float4 q0 = make_float4(q0p[0], q0p[1], q0p[2], q0p[3]);
    double v0x = v0p[0], v0y = v0p[1], v0z = v0p[2];
    double p0x = p0p[0], p0y = p0p[1], p0z = p0p[2];
    const double gz = -(double)GRAV;
    for (int k = 0; k < 8; k++) {
        int c = 8*t + k;
        float4 qc = qnorm4(qmul4(q0, ex.dq));
        double rx, ry, rz;
        qrotd(q0, ex.Ax, ex.Ay, ex.Az, rx, ry, rz);
        double vx = v0x + rx, vy = v0y + ry, vz = v0z + rz + gz * ex.T;
        qrotd(q0, ex.Px, ex.Py, ex.Pz, rx, ry, rz);
        double px = p0x + v0x * ex.T + rx;
        double py = p0y + v0y * ex.T + ry;
        double pz = p0z + v0z * ex.T + rz + gz * ex.G;
        g_sq[c] = qc;
        g_sv[3*c] = vx; g_sv[3*c+1] = vy; g_sv[3*c+2] = vz;
        g_sp[3*c] = px; g_sp[3*c+1] = py; g_sp[3*c+2] = pz;
        ex = dcombine(ex, dload(c));
    }
}

// ---------------- kernel 3: replay to sync points + error terms ----------------
__global__ void k_sync(const int* __restrict__ sync, const float* __restrict__ prot,
                       const float* __restrict__ ptrn) {
    int m = blockIdx.x * blockDim.x + threadIdx.x;
    if (m >= MM) return;
    int i = sync[m];
    int c = i >> LOG_L;
    int r = i & (LL - 1);
    float4 q = g_sq[c];
    const float4* base = g_pack + 2 * (c << LOG_L);
    float vx=0.f, vy=0.f, vz=0.f, px=0.f, py=0.f, pz=0.f, tel=0.f;
    for (int j = 0; j <= r; j++) {
        float4 dqi = base[2*j];
        float4 a4  = base[2*j+1];
        float3 aw = qrot3(q, make_float3(a4.x, a4.y, a4.z));
        aw.z -= GRAV;
        float dt = a4.w;
        float h  = 0.5f * dt * dt;
        px += vx*dt + aw.x*h;  py += vy*dt + aw.y*h;  pz += vz*dt + aw.z*h;
        vx += aw.x*dt;  vy += aw.y*dt;  vz += aw.z*dt;
        tel += dt;
        q = qmul4(q, dqi);
    }
    q = qnorm4(q);
    double Pxx = g_sp[3*c]   + g_sv[3*c]  * (double)tel + (double)px;
    double Pyy = g_sp[3*c+1] + g_sv[3*c+1]* (double)tel + (double)py;
    double Pzz = g_sp[3*c+2] + g_sv[3*c+2]* (double)tel + (double)pz;

    float4 pq = make_float4(prot[4*m], prot[4*m+1], prot[4*m+2], prot[4*m+3]);
    float4 rel = qmul4(make_float4(-pq.x, -pq.y, -pq.z, pq.w), q);
    float nn2 = rel.x*rel.x + rel.y*rel.y + rel.z*rel.z;
    float nn = sqrtf(nn2);
    float theta = 2.0f * atan2f(nn, rel.w);
    float scale = (nn < 1e-7f) ? 2.0f : theta / fmaxf(nn, 1e-12f);
    double lsq = (double)(nn2 * scale * scale);

    float dx = ptrn[3*m+0] - (float)Pxx;
    float dy = ptrn[3*m+1] - (float)Pyy;
    float dz = ptrn[3*m+2] - (float)Pzz;
    g_part[m]      = lsq;
    g_part[MM + m] = (double)dx*dx + (double)dy*dy + (double)dz*dz;
}

// ---------------- kernel 4: deterministic reduction ----------------
__global__ void k_reduce(float* __restrict__ out) {
    __shared__ double s1[1024];
    __shared__ double s2[1024];
    int t = threadIdx.x;
    s1[t] = g_part[t] + g_part[t + 1024];
    s2[t] = g_part[2*MM - 2048 + t] + g_part[2*MM - 1024 + t]; // = g_part[2048+t] + g_part[3072+t]
    __syncthreads();
    for (int off = 512; off > 0; off >>= 1) {
        if (t < off) { s1[t] += s1[t + off]; s2[t] += s2[t + off]; }
        __syncthreads();
    }
    if (t == 0) out[0] = (float)(sqrt(s1[0]) + s2[0] / (3.0 * (double)MM));
}

// ---------------- launch ----------------
extern "C" void kernel_launch(void* const* d_in, const int* in_sizes, int n_in,
                              void* d_out, int out_size) {
    const float* acc  = (const float*)d_in[0];
    const float* gyr  = (const float*)d_in[1];
    const float* ab   = (const float*)d_in[2];
    const float* gb   = (const float*)d_in[3];
    const float* dts  = (const float*)d_in[4];
    const float* q0   = (const float*)d_in[5];
    const float* p0   = (const float*)d_in[6];
    const float* v0   = (const float*)d_in[7];
    const float* prot = (const float*)d_in[8];
    const float* ptrn = (const float*)d_in[9];
    const int*   sync = (const int*)d_in[10];

    k_pack  <<<NN/256, 256>>>(acc, gyr, ab, gb, dts);
    k_chunk <<<CC/128, 128>>>();
    k_scan  <<<1, 256>>>(q0, p0, v0);
    k_sync  <<<MM/128, 128>>>(sync, prot, ptrn);
    k_reduce<<<1, 1024>>>((float*)d_out);
}

// round 2
// speedup vs baseline: 3.1931x; 3.1931x over previous
#include <cuda_runtime.h>
#include <math.h>

#define NN 262144
#define LL 128
#define LOG_L 7
#define CC (NN / LL)      // 2048 chunks
#define GG 64             // 64 groups of 32 chunks
#define MM 2048
#define GRAV 9.81007f

struct S12 { float4 dq; float Ax,Ay,Az,Px,Py,Pz,T,G; };
struct DS  { float4 dq; double Ax,Ay,Az,Px,Py,Pz,T,G; };

__device__ float4 g_dq[NN];     // per-step exp_so3 quaternion
__device__ float4 g_adt[NN];    // a.xyz (bias-corrected), dt
__device__ float4 g_s0[CC];     // chunk summary: dq
__device__ float4 g_s1[CC];     // Ax,Ay,Az,T
__device__ float4 g_s2[CC];     // Px,Py,Pz,G
__device__ DS g_incl[CC];       // within-group inclusive scans (double)
__device__ DS g_gt[GG];         // group totals
__device__ DS g_gp[GG];         // group exclusive prefixes
__device__ float4 g_sq[CC];     // chunk-start rotation (world)
__device__ double g_sv[3 * CC];
__device__ double g_sp[3 * CC];
__device__ double g_part[2 * MM];

// ---------------- quaternion helpers ----------------
__device__ __forceinline__ float4 qmul4(float4 q, float4 r) {
    return make_float4(
        q.w*r.x + q.x*r.w + q.y*r.z - q.z*r.y,
        q.w*r.y - q.x*r.z + q.y*r.w + q.z*r.x,
        q.w*r.z + q.x*r.y - q.y*r.x + q.z*r.w,
        q.w*r.w - q.x*r.x - q.y*r.y - q.z*r.z);
}
__device__ __forceinline__ float4 qnorm4(float4 q) {
    float n = rsqrtf(q.x*q.x + q.y*q.y + q.z*q.z + q.w*q.w);
    return make_float4(q.x*n, q.y*n, q.z*n, q.w*n);
}
__device__ __forceinline__ float3 qrot3(float4 q, float3 v) {
    float tx = 2.0f*(q.y*v.z - q.z*v.y);
    float ty = 2.0f*(q.z*v.x - q.x*v.z);
    float tz = 2.0f*(q.x*v.y - q.y*v.x);
    return make_float3(
        v.x + q.w*tx + (q.y*tz - q.z*ty),
        v.y + q.w*ty + (q.z*tx - q.x*tz),
        v.z + q.w*tz + (q.x*ty - q.y*tx));
}
__device__ __forceinline__ void qrotd(float4 qf, double vx, double vy, double vz,
                                      double& ox, double& oy, double& oz) {
    double qx = qf.x, qy = qf.y, qz = qf.z, qw = qf.w;
    double tx = 2.0*(qy*vz - qz*vy);
    double ty = 2.0*(qz*vx - qx*vz);
    double tz = 2.0*(qx*vy - qy*vx);
    ox = vx + qw*tx + (qy*tz - qz*ty);
    oy = vy + qw*ty + (qz*tx - qx*tz);
    oz = vz + qw*tz + (qx*ty - qy*tx);
}

// ---------------- float summary algebra ----------------
__device__ __forceinline__ S12 sident() {
    S12 s; s.dq = make_float4(0.f,0.f,0.f,1.f);
    s.Ax=s.Ay=s.Az=s.Px=s.Py=s.Pz=0.f; s.T=s.G=0.f; return s;
}
__device__ __forceinline__ S12 scomb(const S12& a, const S12& b) {
    S12 o;
    o.T = a.T + b.T;
    o.G = a.G + a.T*b.T + b.G;
    float3 rA = qrot3(a.dq, make_float3(b.Ax, b.Ay, b.Az));
    o.Ax = a.Ax + rA.x;  o.Ay = a.Ay + rA.y;  o.Az = a.Az + rA.z;
    float3 rP = qrot3(a.dq, make_float3(b.Px, b.Py, b.Pz));
    o.Px = a.Px + a.Ax*b.T + rP.x;
    o.Py = a.Py + a.Ay*b.T + rP.y;
    o.Pz = a.Pz + a.Az*b.T + rP.z;
    o.dq = qmul4(a.dq, b.dq);
    return o;
}
#define WALL 0xffffffffu
__device__ __forceinline__ S12 shfl_down_S(const S12& s, int off) {
    S12 r;
    r.dq.x = __shfl_down_sync(WALL, s.dq.x, off);
    r.dq.y = __shfl_down_sync(WALL, s.dq.y, off);
    r.dq.z = __shfl_down_sync(WALL, s.dq.z, off);
    r.dq.w = __shfl_down_sync(WALL, s.dq.w, off);
    r.Ax = __shfl_down_sync(WALL, s.Ax, off);
    r.Ay = __shfl_down_sync(WALL, s.Ay, off);
    r.Az = __shfl_down_sync(WALL, s.Az, off);
    r.Px = __shfl_down_sync(WALL, s.Px, off);
    r.Py = __shfl_down_sync(WALL, s.Py, off);
    r.Pz = __shfl_down_sync(WALL, s.Pz, off);
    r.T  = __shfl_down_sync(WALL, s.T,  off);
    r.G  = __shfl_down_sync(WALL, s.G,  off);
    return r;
}
// ordered warp fold: lane0 ends with combine of lanes 0..31 in order
__device__ __forceinline__ S12 warp_fold(S12 s) {
#pragma unroll
    for (int off = 1; off < 32; off <<= 1) {
        S12 o = shfl_down_S(s, off);
        s = scomb(s, o);
    }
    return s;  // valid at lane 0
}

// ---------------- double summary algebra ----------------
__device__ __forceinline__ DS dident() {
    DS d; d.dq = make_float4(0.f,0.f,0.f,1.f);
    d.Ax=d.Ay=d.Az=d.Px=d.Py=d.Pz=0.0; d.T=d.G=0.0; return d;
}
__device__ __forceinline__ DS dcomb(const DS& a, const DS& b) {
    DS o;
    o.T = a.T + b.T;
    o.G = a.G + a.T * b.T + b.G;
    double rx, ry, rz;
    qrotd(a.dq, b.Ax, b.Ay, b.Az, rx, ry, rz);
    o.Ax = a.Ax + rx;  o.Ay = a.Ay + ry;  o.Az = a.Az + rz;
    qrotd(a.dq, b.Px, b.Py, b.Pz, rx, ry, rz);
    o.Px = a.Px + a.Ax * b.T + rx;
    o.Py = a.Py + a.Ay * b.T + ry;
    o.Pz = a.Pz + a.Az * b.T + rz;
    o.dq = qnorm4(qmul4(a.dq, b.dq));
    return o;
}
__device__ __forceinline__ DS shfl_up_D(const DS& s, int off) {
    DS r;
    r.dq.x = __shfl_up_sync(WALL, s.dq.x, off);
    r.dq.y = __shfl_up_sync(WALL, s.dq.y, off);
    r.dq.z = __shfl_up_sync(WALL, s.dq.z, off);
    r.dq.w = __shfl_up_sync(WALL, s.dq.w, off);
    r.Ax = __shfl_up_sync(WALL, s.Ax, off);
    r.Ay = __shfl_up_sync(WALL, s.Ay, off);
    r.Az = __shfl_up_sync(WALL, s.Az, off);
    r.Px = __shfl_up_sync(WALL, s.Px, off);
    r.Py = __shfl_up_sync(WALL, s.Py, off);
    r.Pz = __shfl_up_sync(WALL, s.Pz, off);
    r.T  = __shfl_up_sync(WALL, s.T,  off);
    r.G  = __shfl_up_sync(WALL, s.G,  off);
    return r;
}

// ---------------- kernel 1: fused pack + per-chunk summary (warp per chunk) ----------------
__global__ void k_chunk(const float* __restrict__ acc, const float* __restrict__ gyr,
                        const float* __restrict__ ab,  const float* __restrict__ gb,
                        const float* __restrict__ dts) {
    int w    = (blockIdx.x * blockDim.x + threadIdx.x) >> 5;   // chunk id
    int lane = threadIdx.x & 31;
    float abx = __ldg(&ab[0]), aby = __ldg(&ab[1]), abz = __ldg(&ab[2]);
    float gbx = __ldg(&gb[0]), gby = __ldg(&gb[1]), gbz = __ldg(&gb[2]);
    S12 carry = sident();
#pragma unroll
    for (int it = 0; it < 4; it++) {
        int idx = (w << LOG_L) + (it << 5) + lane;
        float ax = acc[3*idx+0] - abx;
        float ay = acc[3*idx+1] - aby;
        float az = acc[3*idx+2] - abz;
        float dt = dts[idx];
        float px = (gyr[3*idx+0] - gbx) * dt;
        float py = (gyr[3*idx+1] - gby) * dt;
        float pz = (gyr[3*idx+2] - gbz) * dt;
        float th2 = px*px + py*py + pz*pz;
        float half = 0.5f * sqrtf(th2);
        float h2 = half * half;
        float sc;
        if (half > 1e-3f) sc = sinf(half) / half;
        else              sc = 1.0f - h2*(1.0f/6.0f)*(1.0f - h2*0.05f);
        float k = 0.5f * sc;
        float4 dq = make_float4(px*k, py*k, pz*k, cosf(half));
        g_dq[idx]  = dq;
        g_adt[idx] = make_float4(ax, ay, az, dt);
        S12 s;
        s.dq = dq;
        s.T  = dt;
        s.G  = 0.5f * dt * dt;
        float h = 0.5f * dt * dt;
        s.Ax = ax*dt;  s.Ay = ay*dt;  s.Az = az*dt;
        s.Px = ax*h;   s.Py = ay*h;   s.Pz = az*h;
        s = warp_fold(s);            // lane0: total of these 32 steps
        carry = (it == 0) ? s : scomb(carry, s);  // only lane0's value matters
    }
    if (lane == 0) {
        carry.dq = qnorm4(carry.dq);
        g_s0[w] = carry.dq;
        g_s1[w] = make_float4(carry.Ax, carry.Ay, carry.Az, carry.T);
        g_s2[w] = make_float4(carry.Px, carry.Py, carry.Pz, carry.G);
    }
}

// ---------------- kernel 2a: within-group inclusive scan (warp per 32 chunks, double) ----------------
__global__ void kS1() {
    int g    = (blockIdx.x * blockDim.x + threadIdx.x) >> 5;
    int lane = threadIdx.x & 31;
    int c = (g << 5) + lane;
    float4 s0 = g_s0[c], s1 = g_s1[c], s2 = g_s2[c];
    DS d;
    d.dq = s0;
    d.Ax = s1.x; d.Ay = s1.y; d.Az = s1.z; d.T = s1.w;
    d.Px = s2.x; d.Py = s2.y; d.Pz = s2.z; d.G = s2.w;
#pragma unroll
    for (int off = 1; off < 32; off <<= 1) {
        DS o = shfl_up_D(d, off);
        if (lane >= off) d = dcomb(o, d);
    }
    g_incl[c] = d;
    if (lane == 31) g_gt[g] = d;
}

// ---------------- kernel 2b: scan group totals (1 warp) ----------------
__global__ void kS2() {
    int lane = threadIdx.x;
    DS a = g_gt[2*lane];
    DS b = g_gt[2*lane+1];
    DS t = dcomb(a, b);
#pragma unroll
    for (int off = 1; off < 32; off <<= 1) {
        DS o = shfl_up_D(t, off);
        if (lane >= off) t = dcomb(o, t);
    }
    DS ex = shfl_up_D(t, 1);
    if (lane == 0) ex = dident();
    g_gp[2*lane]   = ex;
    g_gp[2*lane+1] = dcomb(ex, a);
}

// ---------------- kernel 2c: apply -> chunk-start states ----------------
__global__ void kS3(const float* __restrict__ q0p, const float* __restrict__ p0p,
                    const float* __restrict__ v0p) {
    int c = blockIdx.x * blockDim.x + threadIdx.x;
    if (c >= CC) return;
    int g = c >> 5;
    DS ex = (c & 31) ? dcomb(g_gp[g], g_incl[c-1]) : g_gp[g];
    float4 q0 = make_float4(q0p[0], q0p[1], q0p[2], q0p[3]);
    double v0x = v0p[0], v0y = v0p[1], v0z = v0p[2];
    double p0x = p0p[0], p0y = p0p[1], p0z = p0p[2];
    const double gz = -(double)GRAV;
    float4 qc = qnorm4(qmul4(q0, ex.dq));
    double rx, ry, rz;
    qrotd(q0, ex.Ax, ex.Ay, ex.Az, rx, ry, rz);
    double vx = v0x + rx, vy = v0y + ry, vz = v0z + rz + gz * ex.T;
    qrotd(q0, ex.Px, ex.Py, ex.Pz, rx, ry, rz);
    double px = p0x + v0x * ex.T + rx;
    double py = p0y + v0y * ex.T + ry;
    double pz = p0z + v0z * ex.T + rz + gz * ex.G;
    g_sq[c] = qc;
    g_sv[3*c] = vx; g_sv[3*c+1] = vy; g_sv[3*c+2] = vz;
    g_sp[3*c] = px; g_sp[3*c+1] = py; g_sp[3*c+2] = pz;
}

// ---------------- kernel 3: sync-point evaluation (warp per sync point) ----------------
__global__ void k_sync(const int* __restrict__ sync, const float* __restrict__ prot,
                       const float* __restrict__ ptrn) {
    int w    = (blockIdx.x * blockDim.x + threadIdx.x) >> 5;   // sync id
    int lane = threadIdx.x & 31;
    int i  = sync[w];
    int c  = i >> LOG_L;
    int rr = i & (LL - 1);
    int base = c << LOG_L;
    int ng = (rr >> 5) + 1;
    S12 carry = sident();
    for (int it = 0; it < ng; it++) {
        int j = (it << 5) + lane;
        S12 s;
        if (j <= rr) {
            float4 dq = g_dq[base + j];
            float4 a4 = g_adt[base + j];
            float dt = a4.w;
            float h  = 0.5f * dt * dt;
            s.dq = dq;
            s.T = dt;  s.G = h;
            s.Ax = a4.x*dt;  s.Ay = a4.y*dt;  s.Az = a4.z*dt;
            s.Px = a4.x*h;   s.Py = a4.y*h;   s.Pz = a4.z*h;
        } else {
            s = sident();
        }
        s = warp_fold(s);
        carry = (it == 0) ? s : scomb(carry, s);
    }
    if (lane == 0) {
        float4 qc = g_sq[c];
        float4 q = qnorm4(qmul4(qc, carry.dq));
        double tel = (double)carry.T;
        const double gz = -(double)GRAV;
        double rx, ry, rz;
        qrotd(qc, carry.Px, carry.Py, carry.Pz, rx, ry, rz);
        double Pxx = g_sp[3*c]   + g_sv[3*c]  * tel + rx;
        double Pyy = g_sp[3*c+1] + g_sv[3*c+1]* tel + ry;
        double Pzz = g_sp[3*c+2] + g_sv[3*c+2]* tel + rz + gz * (double)carry.G;

        float4 pq = make_float4(prot[4*w], prot[4*w+1], prot[4*w+2], prot[4*w+3]);
        float4 rel = qmul4(make_float4(-pq.x, -pq.y, -pq.z, pq.w), q);
        float nn2 = rel.x*rel.x + rel.y*rel.y + rel.z*rel.z;
        float nn = sqrtf(nn2);
        float theta = 2.0f * atan2f(nn, rel.w);
        float scale = (nn < 1e-7f) ? 2.0f : theta / fmaxf(nn, 1e-12f);
        double lsq = (double)(nn2 * scale * scale);

        float dx = ptrn[3*w+0] - (float)Pxx;
        float dy = ptrn[3*w+1] - (float)Pyy;
        float dz = ptrn[3*w+2] - (float)Pzz;
        g_part[w]      = lsq;
        g_part[MM + w] = (double)dx*dx + (double)dy*dy + (double)dz*dz;
    }
}

// ---------------- kernel 4: deterministic reduction ----------------
__global__ void k_reduce(float* __restrict__ out) {
    __shared__ double s1[1024];
    __shared__ double s2[1024];
    int t = threadIdx.x;
    s1[t] = g_part[t] + g_part[t + 1024];
    s2[t] = g_part[2048 + t] + g_part[3072 + t];
    __syncthreads();
    for (int off = 512; off > 0; off >>= 1) {
        if (t < off) { s1[t] += s1[t + off]; s2[t] += s2[t + off]; }
        __syncthreads();
    }
    if (t == 0) out[0] = (float)(sqrt(s1[0]) + s2[0] / (3.0 * (double)MM));
}

// ---------------- launch ----------------
extern "C" void kernel_launch(void* const* d_in, const int* in_sizes, int n_in,
                              void* d_out, int out_size) {
    const float* acc  = (const float*)d_in[0];
    const float* gyr  = (const float*)d_in[1];
    const float* ab   = (const float*)d_in[2];
    const float* gb   = (const float*)d_in[3];
    const float* dts  = (const float*)d_in[4];
    const float* q0   = (const float*)d_in[5];
    const float* p0   = (const float*)d_in[6];
    const float* v0   = (const float*)d_in[7];
    const float* prot = (const float*)d_in[8];
    const float* ptrn = (const float*)d_in[9];
    const int*   sync = (const int*)d_in[10];

    k_chunk <<<CC*32/256, 256>>>(acc, gyr, ab, gb, dts);   // 256 blocks, warp/chunk
    kS1     <<<GG*32/256, 256>>>();                        // 8 blocks
    kS2     <<<1, 32>>>();
    kS3     <<<CC/256, 256>>>(q0, p0, v0);
    k_sync  <<<MM*32/256, 256>>>(sync, prot, ptrn);        // 256 blocks, warp/sync
    k_reduce<<<1, 1024>>>((float*)d_out);
}